// round 6
// baseline (speedup 1.0000x reference)
#include <cuda_runtime.h>
#include <cstdint>

#define NUM_USERS 100000
#define NUM_ITEMS 50000
#define DIM 64
#define NUM_REL 5
#define MAX_EDGES 2000000
#define BIN_CAP 192

typedef unsigned long long ull;

__device__ float g_Tf[(size_t)NUM_ITEMS * NUM_REL * DIM];   // 64 MB fp32
__device__ float g_bi[(size_t)NUM_ITEMS * 8];               // stride 8
__device__ int   g_idx64;
__device__ int   g_cnt[NUM_ITEMS];
__device__ int2  g_pairs[(size_t)NUM_ITEMS * BIN_CAP];      // (user, orig_e) 76.8 MB

// ---------------------------------------------------------------------------
// f32x2 helpers (Blackwell packed fp32 pipe)
// ---------------------------------------------------------------------------
__device__ __forceinline__ void fma2(ull& d, ull a, ull b) {
    asm("fma.rn.f32x2 %0, %1, %2, %0;" : "+l"(d) : "l"(a), "l"(b));
}
__device__ __forceinline__ ull dup2(float v) {
    ull p; asm("mov.b64 %0, {%1, %1};" : "=l"(p) : "f"(v)); return p;
}
__device__ __forceinline__ ull pack2(float x, float y) {
    ull p; asm("mov.b64 %0, {%1, %2};" : "=l"(p) : "f"(x), "f"(y)); return p;
}
__device__ __forceinline__ float2 unpack2(ull p) {
    float2 r; asm("mov.b64 {%0, %1}, %2;" : "=f"(r.x), "=f"(r.y) : "l"(p)); return r;
}

// ---------------------------------------------------------------------------
// prep: zero bin counters, detect index width.
// ---------------------------------------------------------------------------
__global__ void prep_kernel(const void* __restrict__ eu) {
    int gid = blockIdx.x * blockDim.x + threadIdx.x;
    if (gid == 0) {
        const int* p = (const int*)eu;
        int is64 = 1;
        #pragma unroll
        for (int j = 1; j < 16; j += 2)
            if (p[j] != 0) is64 = 0;
        g_idx64 = is64;
    }
    if (gid < NUM_ITEMS) g_cnt[gid] = 0;
}

// ---------------------------------------------------------------------------
// scatter: one pass, fixed-capacity bins.
// ---------------------------------------------------------------------------
__global__ void scatter_kernel(const void* __restrict__ edge_u,
                               const void* __restrict__ edge_i, int E) {
    int e = blockIdx.x * blockDim.x + threadIdx.x;
    if (e >= E) return;
    int user, item;
    if (g_idx64) {
        user = (int)__ldg((const long long*)edge_u + e);
        item = (int)__ldg((const long long*)edge_i + e);
    } else {
        user = __ldg((const int*)edge_u + e);
        item = __ldg((const int*)edge_i + e);
    }
    int pos = atomicAdd(&g_cnt[item], 1);
    if (pos < BIN_CAP)
        g_pairs[(size_t)item * BIN_CAP + pos] = make_int2(user, e);
}

// ---------------------------------------------------------------------------
// Precompute Tf (register-tiled GEMM, f32x2 FMA) + fused bi.  fp32 output.
// TILE 64 items, 512 threads: thread (g=tid>>4 in 0..31, c=tid&15) owns
// items {2g, 2g+1} x cols {4c..4c+3}.
// ---------------------------------------------------------------------------
#define TILE_ITEMS 64
__global__ __launch_bounds__(512) void precompute_kernel(
        const float* __restrict__ ifeat,
        const float* __restrict__ W,
        const float* __restrict__ b) {
    __shared__ ull   As2[TILE_ITEMS * DIM];   // duplicated {a,a} pairs, 32 KB
    __shared__ float Ws[DIM * DIM];           // one relation's W, 16 KB

    int tid   = threadIdx.x;
    int item0 = blockIdx.x * TILE_ITEMS;
    int c = tid & 15;
    int g = tid >> 4;   // 0..31 -> items 2g, 2g+1

    for (int idx = tid; idx < TILE_ITEMS * DIM; idx += 512) {
        int it = idx >> 6, d = idx & 63;
        int gi = item0 + it;
        if (gi >= NUM_ITEMS) gi = NUM_ITEMS - 1;
        As2[idx] = dup2(__ldg(ifeat + (size_t)gi * DIM + d));
    }
    __syncthreads();

    // fused bi: 320 (item, rel) dots
    if (tid < TILE_ITEMS * NUM_REL) {
        int it = tid / NUM_REL;
        int r  = tid - it * NUM_REL;
        int gi = item0 + it;
        if (gi < NUM_ITEMS) {
            const float* brow = b + (size_t)r * DIM;
            float s = 0.0f;
            #pragma unroll 16
            for (int d = 0; d < DIM; d++) {
                float2 a = unpack2(As2[it * DIM + d]);
                s = fmaf(a.x, __ldg(brow + d), s);
            }
            g_bi[(size_t)gi * 8 + r] = s;
        }
    }

    for (int r = 0; r < NUM_REL; r++) {
        __syncthreads();
        for (int idx = tid; idx < DIM * DIM / 4; idx += 512)
            ((float4*)Ws)[idx] =
                __ldg((const float4*)(W + (size_t)r * DIM * DIM) + idx);
        __syncthreads();

        ull acc[2][2] = {};
        #pragma unroll 8
        for (int d = 0; d < DIM; d += 2) {
            ulonglong2 w0 = *(const ulonglong2*)(Ws + (d + 0) * DIM + c * 4);
            ulonglong2 w1 = *(const ulonglong2*)(Ws + (d + 1) * DIM + c * 4);
            #pragma unroll
            for (int i = 0; i < 2; i++) {
                ulonglong2 a = *(const ulonglong2*)(As2 + (g * 2 + i) * DIM + d);
                fma2(acc[i][0], a.x, w0.x);
                fma2(acc[i][1], a.x, w0.y);
                fma2(acc[i][0], a.y, w1.x);
                fma2(acc[i][1], a.y, w1.y);
            }
        }

        #pragma unroll
        for (int i = 0; i < 2; i++) {
            int gi = item0 + g * 2 + i;
            if (gi < NUM_ITEMS) {
                float2 p0 = unpack2(acc[i][0]);
                float2 p1 = unpack2(acc[i][1]);
                *(float4*)(g_Tf + ((size_t)gi * NUM_REL + r) * DIM + c * 4) =
                    make_float4(p0.x, p0.y, p1.x, p1.y);
            }
        }
    }
}

// ---------------------------------------------------------------------------
// Binned edge kernel: one warp per item; Ti row + bi register-resident.
// 4 edge slots x 8 lanes; lane sl owns dims 8sl..8sl+7.
// ---------------------------------------------------------------------------
__global__ __launch_bounds__(256) void edge_kernel(
        const float* __restrict__ ufeat, float* __restrict__ out) {
    int item = (blockIdx.x * blockDim.x + threadIdx.x) >> 5;
    if (item >= NUM_ITEMS) return;
    int cnt = g_cnt[item];
    if (cnt == 0) return;
    if (cnt > BIN_CAP) cnt = BIN_CAP;
    const int2* bin = g_pairs + (size_t)item * BIN_CAP;

    int lane = threadIdx.x & 31;
    int sl   = lane & 7;
    int slot = lane >> 3;
    unsigned grpmask = 0xFFu << (slot * 8);

    // Preload Ti row (fp32) -> f32x2 register pairs. 8 floats per rel per lane.
    ull tf[NUM_REL][4];
    #pragma unroll
    for (int r = 0; r < NUM_REL; r++) {
        const float4* p = (const float4*)(g_Tf + ((size_t)item * NUM_REL + r) * DIM) + sl * 2;
        float4 v0 = __ldg(p);
        float4 v1 = __ldg(p + 1);
        tf[r][0] = pack2(v0.x, v0.y);
        tf[r][1] = pack2(v0.z, v0.w);
        tf[r][2] = pack2(v1.x, v1.y);
        tf[r][3] = pack2(v1.z, v1.w);
    }
    float bi_l = __ldg(g_bi + (size_t)item * 8 + sl);

    #pragma unroll 2
    for (int j = slot; j < cnt; j += 4) {
        int2 pr = __ldg(bin + j);                       // (user, orig_e)
        const float4* up = (const float4*)ufeat + (size_t)pr.x * 16 + sl * 2;
        float4 u0 = __ldg(up);
        float4 u1 = __ldg(up + 1);
        ull uf0 = pack2(u0.x, u0.y);
        ull uf1 = pack2(u0.z, u0.w);
        ull uf2 = pack2(u1.x, u1.y);
        ull uf3 = pack2(u1.z, u1.w);

        float s[NUM_REL];
        #pragma unroll
        for (int r = 0; r < NUM_REL; r++) {
            ull acc = 0;
            fma2(acc, tf[r][0], uf0);
            fma2(acc, tf[r][1], uf1);
            fma2(acc, tf[r][2], uf2);
            fma2(acc, tf[r][3], uf3);
            float2 p = unpack2(acc);
            s[r] = p.x + p.y;
        }

        #pragma unroll
        for (int off = 4; off > 0; off >>= 1) {
            #pragma unroll
            for (int r = 0; r < NUM_REL; r++)
                s[r] += __shfl_xor_sync(grpmask, s[r], off);
        }

        if (sl < NUM_REL) {
            float v = (sl == 0) ? s[0] : (sl == 1) ? s[1] : (sl == 2) ? s[2]
                    : (sl == 3) ? s[3] : s[4];
            out[(size_t)pr.y * NUM_REL + sl] = v + bi_l;
        }
    }
}

// ---------------------------------------------------------------------------
extern "C" void kernel_launch(void* const* d_in, const int* in_sizes, int n_in,
                              void* d_out, int out_size) {
    const float* uf  = (const float*)d_in[0];
    const float* itf = (const float*)d_in[1];
    const void*  eu  = d_in[2];
    const void*  ei  = d_in[3];
    const float* W   = (const float*)d_in[4];
    const float* b   = (const float*)d_in[5];
    int E = in_sizes[2];
    if (E > MAX_EDGES) E = MAX_EDGES;

    prep_kernel<<<(NUM_ITEMS + 255) / 256, 256>>>(eu);
    scatter_kernel<<<(E + 255) / 256, 256>>>(eu, ei, E);
    {
        int blocks = (NUM_ITEMS + TILE_ITEMS - 1) / TILE_ITEMS;
        precompute_kernel<<<blocks, 512>>>(itf, W, b);
    }
    {
        int blocks = (NUM_ITEMS * 32 + 255) / 256;   // one warp per item
        edge_kernel<<<blocks, 256>>>(uf, (float*)d_out);
    }
}

// round 7
// speedup vs baseline: 1.6630x; 1.6630x over previous
#include <cuda_runtime.h>
#include <cuda_fp16.h>
#include <cstdint>

#define NUM_USERS 100000
#define NUM_ITEMS 50000
#define DIM 64
#define NUM_REL 5
#define TCOLS (NUM_REL * DIM)   // 320

typedef unsigned long long ull;

__device__ __half g_Ti[(size_t)NUM_ITEMS * TCOLS];          // 32 MB fp16
__device__ __half g_uh[(size_t)NUM_USERS * DIM];            // 12.8 MB fp16
__device__ __half g_ih[(size_t)NUM_ITEMS * DIM];            // 6.4 MB fp16
__device__ __half g_Wp[(size_t)TCOLS * DIM];                // W^T: [col][k], 40 KB
__device__ float  g_bi[(size_t)NUM_ITEMS * 8];              // stride 8
__device__ int    g_idx64;

// ---------------------------------------------------------------------------
// prep: detect index width; convert u, i -> fp16; repack W -> Wp[col][k] fp16
//       where col = r*64 + c and Wp[col][k] = W[r][k][c].
// ---------------------------------------------------------------------------
__global__ void prep_kernel(const float* __restrict__ uf,
                            const float* __restrict__ itf,
                            const float* __restrict__ W,
                            const void* __restrict__ eu) {
    int gid = blockIdx.x * blockDim.x + threadIdx.x;
    if (gid == 0) {
        const int* p = (const int*)eu;
        int is64 = 1;
        #pragma unroll
        for (int j = 1; j < 16; j += 2)
            if (p[j] != 0) is64 = 0;
        g_idx64 = is64;
    }
    // u features: 3.2M half2
    if (gid < NUM_USERS * DIM / 2) {
        float2 v = ((const float2*)uf)[gid];
        ((__half2*)g_uh)[gid] = __floats2half2_rn(v.x, v.y);
    }
    // item features: 1.6M half2
    if (gid < NUM_ITEMS * DIM / 2) {
        float2 v = ((const float2*)itf)[gid];
        ((__half2*)g_ih)[gid] = __floats2half2_rn(v.x, v.y);
    }
    // W transpose-repack: 20480 elements
    if (gid < NUM_REL * DIM * DIM) {
        int r = gid / (DIM * DIM);
        int rem = gid - r * DIM * DIM;
        int k = rem / DIM;       // W row (reduction index)
        int c = rem - k * DIM;   // W col (output index)
        g_Wp[(size_t)(r * DIM + c) * DIM + k] = __float2half_rn(W[gid]);
    }
}

// ---------------------------------------------------------------------------
// bi[item][r] = sum_d b[r,d] * i[item,d]
// ---------------------------------------------------------------------------
__global__ void bi_kernel(const float* __restrict__ ifeat,
                          const float* __restrict__ b) {
    int t = blockIdx.x * blockDim.x + threadIdx.x;
    if (t >= NUM_ITEMS * NUM_REL) return;
    int item = t / NUM_REL;
    int r    = t - item * NUM_REL;
    const float* irow = ifeat + (size_t)item * DIM;
    const float* brow = b + (size_t)r * DIM;
    float s = 0.0f;
    #pragma unroll 16
    for (int d = 0; d < DIM; d++)
        s = fmaf(__ldg(irow + d), __ldg(brow + d), s);
    g_bi[(size_t)item * 8 + r] = s;
}

// ---------------------------------------------------------------------------
// Tensor-core precompute: Ti = ih[50000x64] @ Wp^T  via mma.sync m16n8k16.
// One warp owns 16 items x all 320 cols. 50000 = 3125 warps * 16 exactly.
// A row-major from g_ih; B col-major from g_Wp (k contiguous per col).
// ---------------------------------------------------------------------------
__device__ __forceinline__ void mma16816(float& c0, float& c1, float& c2, float& c3,
                                         unsigned a0, unsigned a1, unsigned a2, unsigned a3,
                                         unsigned b0, unsigned b1) {
    asm volatile(
        "mma.sync.aligned.m16n8k16.row.col.f32.f16.f16.f32 "
        "{%0,%1,%2,%3}, {%4,%5,%6,%7}, {%8,%9}, {%0,%1,%2,%3};"
        : "+f"(c0), "+f"(c1), "+f"(c2), "+f"(c3)
        : "r"(a0), "r"(a1), "r"(a2), "r"(a3), "r"(b0), "r"(b1));
}

__global__ __launch_bounds__(128) void mma_precompute_kernel() {
    int warp = (blockIdx.x * blockDim.x + threadIdx.x) >> 5;
    if (warp >= NUM_ITEMS / 16) return;
    int lane = threadIdx.x & 31;
    int g = lane >> 2;        // 0..7
    int t = lane & 3;         // 0..3
    int item0 = warp * 16;

    // A fragments for all 4 k-steps (rows item0+g, item0+g+8)
    const __half* ihr0 = g_ih + (size_t)(item0 + g) * DIM;
    const __half* ihr1 = g_ih + (size_t)(item0 + g + 8) * DIM;
    unsigned a[4][4];
    #pragma unroll
    for (int ks = 0; ks < 4; ks++) {
        int k0 = ks * 16 + t * 2;
        a[ks][0] = *(const unsigned*)(ihr0 + k0);
        a[ks][1] = *(const unsigned*)(ihr1 + k0);
        a[ks][2] = *(const unsigned*)(ihr0 + k0 + 8);
        a[ks][3] = *(const unsigned*)(ihr1 + k0 + 8);
    }

    #pragma unroll 4
    for (int nt = 0; nt < TCOLS / 8; nt++) {          // 40 n-tiles
        float c0 = 0.f, c1 = 0.f, c2 = 0.f, c3 = 0.f;
        const __half* wp = g_Wp + (size_t)(nt * 8 + g) * DIM;   // B col n = nt*8+g
        #pragma unroll
        for (int ks = 0; ks < 4; ks++) {
            unsigned b0 = __ldg((const unsigned*)(wp + ks * 16 + t * 2));
            unsigned b1 = __ldg((const unsigned*)(wp + ks * 16 + t * 2 + 8));
            mma16816(c0, c1, c2, c3, a[ks][0], a[ks][1], a[ks][2], a[ks][3], b0, b1);
        }
        // D[g][t*2..t*2+1] and D[g+8][t*2..t*2+1] -> fp16 stores
        __half2 h01 = __floats2half2_rn(c0, c1);
        __half2 h23 = __floats2half2_rn(c2, c3);
        int col = nt * 8 + t * 2;
        *(unsigned*)(g_Ti + (size_t)(item0 + g) * TCOLS + col)     = *(unsigned*)&h01;
        *(unsigned*)(g_Ti + (size_t)(item0 + g + 8) * TCOLS + col) = *(unsigned*)&h23;
    }
}

// ---------------------------------------------------------------------------
// Edge kernel (R4, proven): 8 lanes per edge, lane owns 8 halves (one uint4).
// out[e][r] = dot(u[user], Ti[item][r]) + bi[item][r]
// ---------------------------------------------------------------------------
__device__ __forceinline__ float dot8h(uint4 a, uint4 b) {
    float2 a0 = __half22float2(*(const __half2*)&a.x);
    float2 b0 = __half22float2(*(const __half2*)&b.x);
    float2 a1 = __half22float2(*(const __half2*)&a.y);
    float2 b1 = __half22float2(*(const __half2*)&b.y);
    float2 a2 = __half22float2(*(const __half2*)&a.z);
    float2 b2 = __half22float2(*(const __half2*)&b.z);
    float2 a3 = __half22float2(*(const __half2*)&a.w);
    float2 b3 = __half22float2(*(const __half2*)&b.w);
    float s = a0.x * b0.x;
    s = fmaf(a0.y, b0.y, s);
    s = fmaf(a1.x, b1.x, s);
    s = fmaf(a1.y, b1.y, s);
    s = fmaf(a2.x, b2.x, s);
    s = fmaf(a2.y, b2.y, s);
    s = fmaf(a3.x, b3.x, s);
    s = fmaf(a3.y, b3.y, s);
    return s;
}

__global__ void edge_kernel(const void* __restrict__ edge_u,
                            const void* __restrict__ edge_i,
                            float* __restrict__ out,
                            int E) {
    int gid = blockIdx.x * blockDim.x + threadIdx.x;
    int e  = gid >> 3;
    int sl = gid & 7;
    if (e >= E) return;

    long long user, item;
    if (g_idx64) {
        user = __ldg((const long long*)edge_u + e);
        item = __ldg((const long long*)edge_i + e);
    } else {
        user = (long long)__ldg((const int*)edge_u + e);
        item = (long long)__ldg((const int*)edge_i + e);
    }

    uint4 uv = __ldg((const uint4*)g_uh + (size_t)user * 8 + sl);
    const uint4* trow = (const uint4*)g_Ti + (size_t)item * (NUM_REL * 8);

    float a0 = dot8h(uv, __ldg(trow + 0 * 8 + sl));
    float a1 = dot8h(uv, __ldg(trow + 1 * 8 + sl));
    float a2 = dot8h(uv, __ldg(trow + 2 * 8 + sl));
    float a3 = dot8h(uv, __ldg(trow + 3 * 8 + sl));
    float a4 = dot8h(uv, __ldg(trow + 4 * 8 + sl));

    #pragma unroll
    for (int off = 4; off > 0; off >>= 1) {
        a0 += __shfl_xor_sync(0xffffffffu, a0, off);
        a1 += __shfl_xor_sync(0xffffffffu, a1, off);
        a2 += __shfl_xor_sync(0xffffffffu, a2, off);
        a3 += __shfl_xor_sync(0xffffffffu, a3, off);
        a4 += __shfl_xor_sync(0xffffffffu, a4, off);
    }

    if (sl < NUM_REL) {
        float v = (sl == 0) ? a0 : (sl == 1) ? a1 : (sl == 2) ? a2
                : (sl == 3) ? a3 : a4;
        v += __ldg(g_bi + (size_t)item * 8 + sl);
        out[(size_t)e * NUM_REL + sl] = v + 0.0f;
    }
}

// ---------------------------------------------------------------------------
extern "C" void kernel_launch(void* const* d_in, const int* in_sizes, int n_in,
                              void* d_out, int out_size) {
    const float* uf  = (const float*)d_in[0];
    const float* itf = (const float*)d_in[1];
    const void*  eu  = d_in[2];
    const void*  ei  = d_in[3];
    const float* W   = (const float*)d_in[4];
    const float* b   = (const float*)d_in[5];
    int E = in_sizes[2];

    {
        int n = NUM_USERS * DIM / 2;   // largest range covered in prep
        prep_kernel<<<(n + 255) / 256, 256>>>(uf, itf, W, eu);
    }
    {
        int n = NUM_ITEMS * NUM_REL;
        bi_kernel<<<(n + 255) / 256, 256>>>(itf, b);
    }
    {
        int warps = NUM_ITEMS / 16;                 // 3125
        int blocks = (warps + 3) / 4;               // 4 warps / 128-thread block
        mma_precompute_kernel<<<blocks, 128>>>();
    }
    {
        long long total_threads = (long long)E * 8;
        int eblocks = (int)((total_threads + 255) / 256);
        edge_kernel<<<eblocks, 256>>>(eu, ei, (float*)d_out, E);
    }
}